// round 1
// baseline (speedup 1.0000x reference)
#include <cuda_runtime.h>

// Problem constants
constexpr int kN  = 50000;   // nodes
constexpr int kE  = 800000;  // edges per metapath
constexpr int kM  = 4;       // metapaths
constexpr int kH  = 4;       // heads
constexpr int kC  = 32;      // channels per head
constexpr int kIN = 256;     // input dim
constexpr int kD  = 128;     // output dim (H*C)
constexpr int kMN = kM * kN;     // 200000
constexpr int kME = kM * kE;     // 3200000
constexpr int SCAN_T  = 1024;
constexpr int SCAN_NB = (kMN + SCAN_T - 1) / SCAN_T;  // 196

// Scratch (no cudaMalloc allowed -> __device__ globals)
__device__ float g_h[kN * kD];          // projected features, 25.6MB
__device__ float g_adst[kMN * kH];      // per-(m,node,h) dst-side logit term
__device__ float g_asrc[kMN * kH];      // per-(m,node,h) src-side logit term
__device__ int   g_cnt[kMN];            // in-degree histogram
__device__ int   g_rowstart[kMN + 1];   // CSR row offsets
__device__ int   g_cursor[kMN];         // scatter cursors
__device__ int   g_bsum[SCAN_NB];
__device__ int   g_boff[SCAN_NB];
__device__ int   g_csrc[kME];           // CSR: src node per edge slot
__device__ float g_rel[kMN * kD];       // per-relation aggregated output, 102.4MB

// ---------------------------------------------------------------------------
// K1: h = relu(feats @ W + b)   [50000,256]@[256,128]
// 128x128 block tile, BK=16, 256 threads, 8x8 per thread, fp32 SIMT.
// ---------------------------------------------------------------------------
__global__ __launch_bounds__(256, 2) void k_gemm(
    const float* __restrict__ A, const float* __restrict__ W,
    const float* __restrict__ bias)
{
    __shared__ float As[16][132];   // [k][m], padded stride
    __shared__ float Bs[16][128];   // [k][n]

    const int tid  = threadIdx.x;
    const int tr   = tid >> 4;
    const int tc   = tid & 15;
    const int row0 = tr * 8;
    const int col0 = tc * 8;
    const int rowBase = blockIdx.x * 128;

    float acc[8][8];
#pragma unroll
    for (int i = 0; i < 8; i++)
#pragma unroll
        for (int j = 0; j < 8; j++) acc[i][j] = 0.f;

    for (int k0 = 0; k0 < kIN; k0 += 16) {
        // Load A tile: 128x16 = 512 float4, 2 per thread; store transposed.
#pragma unroll
        for (int i = 0; i < 2; i++) {
            int f  = tid + i * 256;
            int r  = f >> 2;
            int c4 = (f & 3) << 2;
            float4 v = make_float4(0.f, 0.f, 0.f, 0.f);
            int gr = rowBase + r;
            if (gr < kN) v = *(const float4*)(A + (long)gr * kIN + k0 + c4);
            As[c4 + 0][r] = v.x; As[c4 + 1][r] = v.y;
            As[c4 + 2][r] = v.z; As[c4 + 3][r] = v.w;
        }
        // Load B tile: 16x128 = 512 float4, 2 per thread.
#pragma unroll
        for (int i = 0; i < 2; i++) {
            int f  = tid + i * 256;
            int kk = f >> 5;
            int n4 = (f & 31) << 2;
            *(float4*)(&Bs[kk][n4]) = *(const float4*)(W + (k0 + kk) * kD + n4);
        }
        __syncthreads();
#pragma unroll
        for (int kk = 0; kk < 16; kk++) {
            float ra[8], rb[8];
            *(float4*)(ra)     = *(const float4*)(&As[kk][row0]);
            *(float4*)(ra + 4) = *(const float4*)(&As[kk][row0 + 4]);
            *(float4*)(rb)     = *(const float4*)(&Bs[kk][col0]);
            *(float4*)(rb + 4) = *(const float4*)(&Bs[kk][col0 + 4]);
#pragma unroll
            for (int i = 0; i < 8; i++)
#pragma unroll
                for (int j = 0; j < 8; j++)
                    acc[i][j] = fmaf(ra[i], rb[j], acc[i][j]);
        }
        __syncthreads();
    }
#pragma unroll
    for (int i = 0; i < 8; i++) {
        int gr = rowBase + row0 + i;
        if (gr < kN) {
            float4 o0, o1;
            o0.x = fmaxf(acc[i][0] + bias[col0 + 0], 0.f);
            o0.y = fmaxf(acc[i][1] + bias[col0 + 1], 0.f);
            o0.z = fmaxf(acc[i][2] + bias[col0 + 2], 0.f);
            o0.w = fmaxf(acc[i][3] + bias[col0 + 3], 0.f);
            o1.x = fmaxf(acc[i][4] + bias[col0 + 4], 0.f);
            o1.y = fmaxf(acc[i][5] + bias[col0 + 5], 0.f);
            o1.z = fmaxf(acc[i][6] + bias[col0 + 6], 0.f);
            o1.w = fmaxf(acc[i][7] + bias[col0 + 7], 0.f);
            *(float4*)(g_h + (long)gr * kD + col0)     = o0;
            *(float4*)(g_h + (long)gr * kD + col0 + 4) = o1;
        }
    }
}

// ---------------------------------------------------------------------------
// K2: per-node logit terms. a_dst[m,n,h] = sum_c h[n,h,c]*attn[m,h,c],
//     a_src uses attn[m,h,C+c]. Warp per node, lane = c.
// ---------------------------------------------------------------------------
__global__ __launch_bounds__(256) void k_alpha(const float* __restrict__ attn)
{
    int gw   = (blockIdx.x * blockDim.x + threadIdx.x) >> 5;
    int lane = threadIdx.x & 31;
    if (gw >= kN) return;
    float h4[4];
#pragma unroll
    for (int k = 0; k < 4; k++) h4[k] = g_h[gw * kD + k * 32 + lane];
#pragma unroll
    for (int m = 0; m < kM; m++) {
#pragma unroll
        for (int k = 0; k < 4; k++) {
            float vl = h4[k] * attn[(m * kH + k) * (2 * kC) + lane];
            float vr = h4[k] * attn[(m * kH + k) * (2 * kC) + kC + lane];
#pragma unroll
            for (int o = 16; o > 0; o >>= 1) {
                vl += __shfl_xor_sync(0xffffffffu, vl, o);
                vr += __shfl_xor_sync(0xffffffffu, vr, o);
            }
            if (lane == 0) {
                g_adst[(m * kN + gw) * kH + k] = vl;
                g_asrc[(m * kN + gw) * kH + k] = vr;
            }
        }
    }
}

// ---------------------------------------------------------------------------
// CSR build: zero / histogram / 3-kernel exclusive scan / scatter
// ---------------------------------------------------------------------------
__global__ void k_zero()
{
    int i = blockIdx.x * blockDim.x + threadIdx.x;
    if (i < kMN) g_cnt[i] = 0;
}

__global__ void k_deg(const int* __restrict__ ei)
{
    int t = blockIdx.x * blockDim.x + threadIdx.x;
    if (t >= kME) return;
    int m = t / kE;
    int e = t - m * kE;
    int dst = ei[(m * 2 + 1) * kE + e];
    atomicAdd(&g_cnt[m * kN + dst], 1);
}

__global__ void k_scan1()
{
    __shared__ int wsum[32];
    int t = threadIdx.x, b = blockIdx.x;
    int i = b * SCAN_T + t;
    int x = (i < kMN) ? g_cnt[i] : 0;
    int lane = t & 31, wid = t >> 5;
    int v = x;
#pragma unroll
    for (int o = 1; o < 32; o <<= 1) {
        int u = __shfl_up_sync(0xffffffffu, v, o);
        if (lane >= o) v += u;
    }
    if (lane == 31) wsum[wid] = v;
    __syncthreads();
    if (wid == 0) {
        int s = wsum[lane];
#pragma unroll
        for (int o = 1; o < 32; o <<= 1) {
            int u = __shfl_up_sync(0xffffffffu, s, o);
            if (lane >= o) s += u;
        }
        wsum[lane] = s;
    }
    __syncthreads();
    int pre  = (wid > 0) ? wsum[wid - 1] : 0;
    int incl = v + pre;
    if (i < kMN) g_rowstart[i] = incl - x;   // exclusive within block
    if (t == SCAN_T - 1) g_bsum[b] = incl;
}

__global__ void k_scan2()
{
    if (threadIdx.x == 0 && blockIdx.x == 0) {
        int run = 0;
        for (int b = 0; b < SCAN_NB; b++) { g_boff[b] = run; run += g_bsum[b]; }
    }
}

__global__ void k_scan3()
{
    int i = blockIdx.x * SCAN_T + threadIdx.x;
    if (i < kMN) {
        int v = g_rowstart[i] + g_boff[blockIdx.x];
        g_rowstart[i] = v;
        g_cursor[i]   = v;
    }
    if (i == 0) g_rowstart[kMN] = kME;
}

__global__ void k_scatter(const int* __restrict__ ei)
{
    int t = blockIdx.x * blockDim.x + threadIdx.x;
    if (t >= kME) return;
    int m = t / kE;
    int e = t - m * kE;
    int src = ei[(m * 2 + 0) * kE + e];
    int dst = ei[(m * 2 + 1) * kE + e];
    int pos = atomicAdd(&g_cursor[m * kN + dst], 1);
    g_csrc[pos] = src;
}

// ---------------------------------------------------------------------------
// K6: per-(metapath,node) softmax-weighted aggregation, warp per (m,n).
// out[n,h,c] = (sum_e w_e * h[src_e,h,c]) / (sum_e w_e),
// w_e = exp(leakyrelu(a_dst + a_src)). No max subtraction (safe range), no
// atomics: register accumulation over the CSR edge list.
// ---------------------------------------------------------------------------
__global__ __launch_bounds__(256) void k_agg()
{
    __shared__ float wsh[8][32][4];
    __shared__ int   ssh[8][32];
    int w    = threadIdx.x >> 5;
    int lane = threadIdx.x & 31;
    int flat = blockIdx.x * 8 + w;
    if (flat >= kMN) return;
    int m = flat / kN;
    int base_mn = m * kN;
    int start = g_rowstart[flat];
    int end   = g_rowstart[flat + 1];
    float4 ad = *(const float4*)(g_adst + flat * 4);
    float acc[4]  = {0.f, 0.f, 0.f, 0.f};
    float dsum[4] = {0.f, 0.f, 0.f, 0.f};

    for (int b0 = start; b0 < end; b0 += 32) {
        int cnt = min(32, end - b0);
        if (lane < cnt) {
            int s = g_csrc[b0 + lane];
            ssh[w][lane] = s;
            float4 as4 = *(const float4*)(g_asrc + (base_mn + s) * 4);
            float l0 = ad.x + as4.x; l0 = l0 > 0.f ? l0 : 0.2f * l0;
            float l1 = ad.y + as4.y; l1 = l1 > 0.f ? l1 : 0.2f * l1;
            float l2 = ad.z + as4.z; l2 = l2 > 0.f ? l2 : 0.2f * l2;
            float l3 = ad.w + as4.w; l3 = l3 > 0.f ? l3 : 0.2f * l3;
            wsh[w][lane][0] = expf(l0);
            wsh[w][lane][1] = expf(l1);
            wsh[w][lane][2] = expf(l2);
            wsh[w][lane][3] = expf(l3);
        }
        __syncwarp();
        for (int j = 0; j < cnt; j++) {
            int s = ssh[w][j];
            const float* hp = g_h + (long)s * kD + lane;
#pragma unroll
            for (int k = 0; k < 4; k++) {
                float wv = wsh[w][j][k];
                dsum[k] += wv;
                acc[k] = fmaf(wv, hp[k * 32], acc[k]);
            }
        }
        __syncwarp();
    }
#pragma unroll
    for (int k = 0; k < 4; k++)
        g_rel[(long)flat * kD + k * 32 + lane] = acc[k] / (dsum[k] + 1e-16f);
}

// ---------------------------------------------------------------------------
// K7: relation attention (beta) + combine + relu. Warp per node.
// ---------------------------------------------------------------------------
__global__ __launch_bounds__(256) void k_beta(
    const float* __restrict__ ral, const float* __restrict__ rar,
    const float* __restrict__ rbias, float* __restrict__ outp)
{
    int gw   = (blockIdx.x * blockDim.x + threadIdx.x) >> 5;
    int lane = threadIdx.x & 31;
    if (gw >= kN) return;
    float hv[4], bl[4];
#pragma unroll
    for (int k = 0; k < 4; k++) {
        hv[k] = g_h[gw * kD + k * 32 + lane];
        float t = hv[k] * ral[k * kC + lane];
        bl[k] = t > 0.f ? t : 0.f;
    }
    float e[5][4], beta[5][4];
#pragma unroll
    for (int r = 0; r < 5; r++) {
#pragma unroll
        for (int k = 0; k < 4; k++) {
            float ev = (r < 4) ? g_rel[((long)(r * kN + gw)) * kD + k * 32 + lane]
                               : hv[k];
            e[r][k] = ev;
            float br = ev * rar[(r * kH + k) * kC + lane];
            br = br > 0.f ? br : 0.f;
            float p = bl[k] * br;
#pragma unroll
            for (int o = 16; o > 0; o >>= 1)
                p += __shfl_xor_sync(0xffffffffu, p, o);
            beta[r][k] = p + rbias[r];
        }
    }
#pragma unroll
    for (int k = 0; k < 4; k++) {
        float mx = beta[0][k];
#pragma unroll
        for (int r = 1; r < 5; r++) mx = fmaxf(mx, beta[r][k]);
        float ex[5], s = 0.f;
#pragma unroll
        for (int r = 0; r < 5; r++) { ex[r] = expf(beta[r][k] - mx); s += ex[r]; }
        float inv = 1.f / s;
        float o = 0.f;
#pragma unroll
        for (int r = 0; r < 5; r++) o += e[r][k] * ex[r] * inv;
        o = o > 0.f ? o : 0.f;
        outp[gw * kD + k * 32 + lane] = o;
    }
}

// ---------------------------------------------------------------------------
extern "C" void kernel_launch(void* const* d_in, const int* in_sizes, int n_in,
                              void* d_out, int out_size)
{
    const float* feats = (const float*)d_in[0];
    const int*   ei    = (const int*)d_in[1];
    const float* W     = (const float*)d_in[2];
    const float* b     = (const float*)d_in[3];
    const float* attn  = (const float*)d_in[4];
    const float* ral   = (const float*)d_in[5];
    const float* rar   = (const float*)d_in[6];
    const float* rbias = (const float*)d_in[7];
    float* outp = (float*)d_out;

    k_gemm<<<(kN + 127) / 128, 256>>>(feats, W, b);
    k_alpha<<<(kN + 7) / 8, 256>>>(attn);
    k_zero<<<(kMN + 255) / 256, 256>>>();
    k_deg<<<(kME + 255) / 256, 256>>>(ei);
    k_scan1<<<SCAN_NB, SCAN_T>>>();
    k_scan2<<<1, 32>>>();
    k_scan3<<<SCAN_NB, SCAN_T>>>();
    k_scatter<<<(kME + 255) / 256, 256>>>(ei);
    k_agg<<<(kMN + 7) / 8, 256>>>();
    k_beta<<<(kN + 7) / 8, 256>>>(ral, rar, rbias, outp);
}

// round 2
// speedup vs baseline: 1.3977x; 1.3977x over previous
#include <cuda_runtime.h>
#include <cuda_bf16.h>

// Problem constants
constexpr int kN  = 50000;   // nodes
constexpr int kE  = 800000;  // edges per metapath
constexpr int kM  = 4;       // metapaths
constexpr int kH  = 4;       // heads
constexpr int kC  = 32;      // channels per head
constexpr int kIN = 256;     // input dim
constexpr int kD  = 128;     // output dim (H*C)
constexpr int kMN = kM * kN;     // 200000
constexpr int kME = kM * kE;     // 3200000
constexpr int PAD = 64;          // bucket capacity (Poisson(16) tail ~1e-20)

constexpr int NGEMM = (kN + 127) / 128;  // 391 gemm blocks
constexpr int NBUK  = 1250;              // bucket-build blocks

// Scratch (__device__ globals; no cudaMalloc allowed)
__device__ float          g_h[kN * kD];       // projected features fp32, 25.6MB
__device__ __nv_bfloat16  g_hb[kN * kD];      // bf16 copy for gather, 12.8MB
__device__ float          g_adst[kMN * kH];   // per-(m,node) dst logit term
__device__ float          g_asrc[kMN * kH];   // per-(m,node) src logit term
__device__ int            g_cnt[kMN];         // per-(m,node) in-degree
__device__ int            g_bsrc[(long)kMN * PAD];  // padded buckets, 51.2MB

// ---------------------------------------------------------------------------
// K0: zero the degree counters
// ---------------------------------------------------------------------------
__global__ void k_zero()
{
    int i = blockIdx.x * blockDim.x + threadIdx.x;
    if (i < kMN) g_cnt[i] = 0;
}

// ---------------------------------------------------------------------------
// K1 (heterogeneous): blocks [0,NGEMM) compute h = relu(feats@W + b) and
// write fp32 + bf16 copies; blocks [NGEMM, NGEMM+NBUK) build the padded
// dst-buckets from edge_index (independent work, overlapped on the SMs).
// ---------------------------------------------------------------------------
__global__ __launch_bounds__(256, 2) void k_fused(
    const float* __restrict__ A, const float* __restrict__ W,
    const float* __restrict__ bias, const int* __restrict__ ei)
{
    __shared__ float As[16][132];   // [k][m], padded stride
    __shared__ float Bs[16][128];   // [k][n]

    if (blockIdx.x >= NGEMM) {
        // ---- bucket build ----
        int t = (blockIdx.x - NGEMM) * 256 + threadIdx.x;
        const int stride = NBUK * 256;
        for (; t < kME; t += stride) {
            int m   = t / kE;
            int e   = t - m * kE;
            int src = ei[(m * 2 + 0) * kE + e];
            int dst = ei[(m * 2 + 1) * kE + e];
            int row = m * kN + dst;
            int pos = atomicAdd(&g_cnt[row], 1);
            if (pos < PAD) g_bsrc[(long)row * PAD + pos] = src;
        }
        return;
    }

    // ---- GEMM ----
    const int tid  = threadIdx.x;
    const int tr   = tid >> 4;
    const int tc   = tid & 15;
    const int row0 = tr * 8;
    const int col0 = tc * 8;
    const int rowBase = blockIdx.x * 128;

    float acc[8][8];
#pragma unroll
    for (int i = 0; i < 8; i++)
#pragma unroll
        for (int j = 0; j < 8; j++) acc[i][j] = 0.f;

    for (int k0 = 0; k0 < kIN; k0 += 16) {
#pragma unroll
        for (int i = 0; i < 2; i++) {
            int f  = tid + i * 256;
            int r  = f >> 2;
            int c4 = (f & 3) << 2;
            float4 v = make_float4(0.f, 0.f, 0.f, 0.f);
            int gr = rowBase + r;
            if (gr < kN) v = *(const float4*)(A + (long)gr * kIN + k0 + c4);
            As[c4 + 0][r] = v.x; As[c4 + 1][r] = v.y;
            As[c4 + 2][r] = v.z; As[c4 + 3][r] = v.w;
        }
#pragma unroll
        for (int i = 0; i < 2; i++) {
            int f  = tid + i * 256;
            int kk = f >> 5;
            int n4 = (f & 31) << 2;
            *(float4*)(&Bs[kk][n4]) = *(const float4*)(W + (k0 + kk) * kD + n4);
        }
        __syncthreads();
#pragma unroll
        for (int kk = 0; kk < 16; kk++) {
            float ra[8], rb[8];
            *(float4*)(ra)     = *(const float4*)(&As[kk][row0]);
            *(float4*)(ra + 4) = *(const float4*)(&As[kk][row0 + 4]);
            *(float4*)(rb)     = *(const float4*)(&Bs[kk][col0]);
            *(float4*)(rb + 4) = *(const float4*)(&Bs[kk][col0 + 4]);
#pragma unroll
            for (int i = 0; i < 8; i++)
#pragma unroll
                for (int j = 0; j < 8; j++)
                    acc[i][j] = fmaf(ra[i], rb[j], acc[i][j]);
        }
        __syncthreads();
    }
#pragma unroll
    for (int i = 0; i < 8; i++) {
        int gr = rowBase + row0 + i;
        if (gr < kN) {
            float o[8];
#pragma unroll
            for (int j = 0; j < 8; j++)
                o[j] = fmaxf(acc[i][j] + bias[col0 + j], 0.f);
            *(float4*)(g_h + (long)gr * kD + col0)     = *(float4*)(o);
            *(float4*)(g_h + (long)gr * kD + col0 + 4) = *(float4*)(o + 4);
            __nv_bfloat16* hb = g_hb + (long)gr * kD + col0;
#pragma unroll
            for (int j = 0; j < 4; j++)
                *(__nv_bfloat162*)(hb + 2 * j) =
                    __floats2bfloat162_rn(o[2 * j], o[2 * j + 1]);
        }
    }
}

// ---------------------------------------------------------------------------
// K2: per-node logit terms. a_dst[m,n,h] = sum_c h[n,h,c]*attn[m,h,c],
//     a_src uses attn[m,h,C+c]. Warp per node, lane = c.
// ---------------------------------------------------------------------------
__global__ __launch_bounds__(256) void k_alpha(const float* __restrict__ attn)
{
    int gw   = (blockIdx.x * blockDim.x + threadIdx.x) >> 5;
    int lane = threadIdx.x & 31;
    if (gw >= kN) return;
    float h4[4];
#pragma unroll
    for (int k = 0; k < 4; k++) h4[k] = g_h[(long)gw * kD + k * 32 + lane];
#pragma unroll
    for (int m = 0; m < kM; m++) {
#pragma unroll
        for (int k = 0; k < 4; k++) {
            float vl = h4[k] * attn[(m * kH + k) * (2 * kC) + lane];
            float vr = h4[k] * attn[(m * kH + k) * (2 * kC) + kC + lane];
#pragma unroll
            for (int o = 16; o > 0; o >>= 1) {
                vl += __shfl_xor_sync(0xffffffffu, vl, o);
                vr += __shfl_xor_sync(0xffffffffu, vr, o);
            }
            if (lane == 0) {
                g_adst[(m * kN + gw) * kH + k] = vl;
                g_asrc[(m * kN + gw) * kH + k] = vr;
            }
        }
    }
}

// ---------------------------------------------------------------------------
// K3: fused aggregation + relation attention. Warp per node.
// Lane l owns channel pairs {2l, 2l+1} (heads 0/1) and {64+2l, 64+2l+1}
// (heads 2/3). For each metapath: softmax-weighted mean of bf16 messages
// (weights fp32, normalization folded: out = sum(w*h)/sum(w)). Then the
// beta relation-softmax entirely in registers; writes final relu'd output.
// ---------------------------------------------------------------------------
__global__ __launch_bounds__(256) void k_aggbeta(
    const float* __restrict__ ral, const float* __restrict__ rar,
    const float* __restrict__ rbias, float* __restrict__ outp)
{
    __shared__ float wsh[8][32][4];
    __shared__ int   ssh[8][32];
    const int w    = threadIdx.x >> 5;
    const int lane = threadIdx.x & 31;
    const int n    = blockIdx.x * 8 + w;
    if (n >= kN) return;

    const int h0 = lane >> 4;        // head for first pair (0 or 1)
    const int h1 = 2 + (lane >> 4);  // head for second pair (2 or 3)
    const int cc = (2 * lane) & 31;  // channel-within-head offset

    const float2 ha = *(const float2*)(g_h + (long)n * kD + 2 * lane);
    const float2 hbv = *(const float2*)(g_h + (long)n * kD + 64 + 2 * lane);
    const __nv_bfloat162* hb2 = (const __nv_bfloat162*)g_hb;

    float2 era[5], erb[5];
    float  bta[5], btb[5];

    for (int m = 0; m < kM; m++) {
        const int row = m * kN + n;
        const float4 ad = *(const float4*)(g_adst + (long)row * 4);
        const int cnt = min(g_cnt[row], PAD);
        const int* __restrict__ bl = g_bsrc + (long)row * PAD;
        float2 a0 = make_float2(0.f, 0.f), a1 = make_float2(0.f, 0.f);
        float d0 = 0.f, d1 = 0.f;

        for (int b0e = 0; b0e < cnt; b0e += 32) {
            const int c = min(32, cnt - b0e);
            if (lane < c) {
                int s = bl[b0e + lane];
                ssh[w][lane] = s;
                float4 as = *(const float4*)(g_asrc + (long)(m * kN + s) * 4);
                float l0 = ad.x + as.x; l0 = l0 > 0.f ? l0 : 0.2f * l0;
                float l1 = ad.y + as.y; l1 = l1 > 0.f ? l1 : 0.2f * l1;
                float l2 = ad.z + as.z; l2 = l2 > 0.f ? l2 : 0.2f * l2;
                float l3 = ad.w + as.w; l3 = l3 > 0.f ? l3 : 0.2f * l3;
                wsh[w][lane][0] = __expf(l0) * 0.f + expf(l0);
                wsh[w][lane][1] = expf(l1);
                wsh[w][lane][2] = expf(l2);
                wsh[w][lane][3] = expf(l3);
            }
            __syncwarp();
            for (int j = 0; j < c; j++) {
                const int s = ssh[w][j];
                const float w0 = wsh[w][j][h0];
                const float w1 = wsh[w][j][h1];
                float2 fa = __bfloat1622float2(hb2[(long)s * 64 + lane]);
                float2 fb = __bfloat1622float2(hb2[(long)s * 64 + 32 + lane]);
                a0.x = fmaf(w0, fa.x, a0.x); a0.y = fmaf(w0, fa.y, a0.y);
                a1.x = fmaf(w1, fb.x, a1.x); a1.y = fmaf(w1, fb.y, a1.y);
                d0 += w0; d1 += w1;
            }
            __syncwarp();
        }
        const float i0 = 1.f / (d0 + 1e-16f);
        const float i1 = 1.f / (d1 + 1e-16f);
        era[m] = make_float2(a0.x * i0, a0.y * i0);
        erb[m] = make_float2(a1.x * i1, a1.y * i1);
    }
    era[4] = ha;   // self relation
    erb[4] = hbv;

    // beta_l = relu(h * rel_attn_l)
    const float2 rla = *(const float2*)(ral + h0 * kC + cc);
    const float2 rlb = *(const float2*)(ral + h1 * kC + cc);
    const float2 bla = make_float2(fmaxf(ha.x * rla.x, 0.f),
                                   fmaxf(ha.y * rla.y, 0.f));
    const float2 blb = make_float2(fmaxf(hbv.x * rlb.x, 0.f),
                                   fmaxf(hbv.y * rlb.y, 0.f));
#pragma unroll
    for (int r = 0; r < 5; r++) {
        const float2 rra = *(const float2*)(rar + ((r * kH + h0) * kC + cc));
        const float2 rrb = *(const float2*)(rar + ((r * kH + h1) * kC + cc));
        float bax = fmaxf(era[r].x * rra.x, 0.f);
        float bay = fmaxf(era[r].y * rra.y, 0.f);
        float bbx = fmaxf(erb[r].x * rrb.x, 0.f);
        float bby = fmaxf(erb[r].y * rrb.y, 0.f);
        float p0 = bla.x * bax + bla.y * bay;
        float p1 = blb.x * bbx + blb.y * bby;
#pragma unroll
        for (int o = 8; o > 0; o >>= 1) {
            p0 += __shfl_xor_sync(0xffffffffu, p0, o);
            p1 += __shfl_xor_sync(0xffffffffu, p1, o);
        }
        bta[r] = p0 + rbias[r];
        btb[r] = p1 + rbias[r];
    }
    // softmax over relations, then combine + relu
    float m0 = bta[0], m1 = btb[0];
#pragma unroll
    for (int r = 1; r < 5; r++) { m0 = fmaxf(m0, bta[r]); m1 = fmaxf(m1, btb[r]); }
    float s0 = 0.f, s1 = 0.f, e0[5], e1[5];
#pragma unroll
    for (int r = 0; r < 5; r++) {
        e0[r] = expf(bta[r] - m0); s0 += e0[r];
        e1[r] = expf(btb[r] - m1); s1 += e1[r];
    }
    const float is0 = 1.f / s0, is1 = 1.f / s1;
    float2 oa = make_float2(0.f, 0.f), ob = make_float2(0.f, 0.f);
#pragma unroll
    for (int r = 0; r < 5; r++) {
        const float w0 = e0[r] * is0, w1 = e1[r] * is1;
        oa.x = fmaf(w0, era[r].x, oa.x); oa.y = fmaf(w0, era[r].y, oa.y);
        ob.x = fmaf(w1, erb[r].x, ob.x); ob.y = fmaf(w1, erb[r].y, ob.y);
    }
    oa.x = fmaxf(oa.x, 0.f); oa.y = fmaxf(oa.y, 0.f);
    ob.x = fmaxf(ob.x, 0.f); ob.y = fmaxf(ob.y, 0.f);
    *(float2*)(outp + (long)n * kD + 2 * lane)      = oa;
    *(float2*)(outp + (long)n * kD + 64 + 2 * lane) = ob;
}

// ---------------------------------------------------------------------------
extern "C" void kernel_launch(void* const* d_in, const int* in_sizes, int n_in,
                              void* d_out, int out_size)
{
    const float* feats = (const float*)d_in[0];
    const int*   ei    = (const int*)d_in[1];
    const float* W     = (const float*)d_in[2];
    const float* b     = (const float*)d_in[3];
    const float* attn  = (const float*)d_in[4];
    const float* ral   = (const float*)d_in[5];
    const float* rar   = (const float*)d_in[6];
    const float* rbias = (const float*)d_in[7];
    float* outp = (float*)d_out;

    k_zero<<<(kMN + 255) / 256, 256>>>();
    k_fused<<<NGEMM + NBUK, 256>>>(feats, W, b, ei);
    k_alpha<<<(kN + 7) / 8, 256>>>(attn);
    k_aggbeta<<<(kN + 7) / 8, 256>>>(ral, rar, rbias, outp);
}

// round 3
// speedup vs baseline: 1.5952x; 1.1413x over previous
#include <cuda_runtime.h>
#include <cuda_bf16.h>

// Problem constants
constexpr int kN  = 50000;   // nodes
constexpr int kE  = 800000;  // edges per metapath
constexpr int kM  = 4;       // metapaths
constexpr int kH  = 4;       // heads
constexpr int kC  = 32;      // channels per head
constexpr int kIN = 256;     // input dim
constexpr int kD  = 128;     // output dim (H*C)
constexpr int kMN = kM * kN;     // 200000
constexpr int kME = kM * kE;     // 3200000
constexpr int PAD = 64;          // bucket capacity (Poisson(16) tail ~1e-20)

constexpr int NGEMM = (kN + 127) / 128;  // 391 gemm blocks
constexpr int NBUK  = 1250;              // bucket-build blocks

// Scratch (__device__ globals; no cudaMalloc allowed)
__device__ float    g_h[kN * kD];        // projected features fp32, 25.6MB
__device__ unsigned g_hpu[kN * 64];      // packed bf16 messages, 12.8MB
                                         // u[2l+0] = bf16x2(h[2l],h[2l+1])
                                         // u[2l+1] = bf16x2(h[64+2l],h[64+2l+1])
__device__ float    g_adst[kMN * kH];    // per-(m,node) dst logit term
__device__ float    g_asrc[kMN * kH];    // per-(m,node) src logit term
__device__ int      g_cnt[kMN];          // per-(m,node) in-degree
__device__ int      g_bsrc[(long)kMN * PAD];  // padded buckets, 51.2MB

// ---------------------------------------------------------------------------
// K0: zero the degree counters
// ---------------------------------------------------------------------------
__global__ void k_zero()
{
    int i = blockIdx.x * blockDim.x + threadIdx.x;
    if (i < kMN) g_cnt[i] = 0;
}

// ---------------------------------------------------------------------------
// K1 (heterogeneous): blocks [0,NGEMM) compute h = relu(feats@W + b) with a
// single-sync double-buffered smem pipeline, writing fp32 + packed-bf16
// copies; blocks [NGEMM, ...) build the padded dst-buckets (overlapped).
// ---------------------------------------------------------------------------
__global__ __launch_bounds__(256, 2) void k_fused(
    const float* __restrict__ A, const float* __restrict__ W,
    const float* __restrict__ bias, const int* __restrict__ ei)
{
    __shared__ float As[2][16][132];   // [buf][k][m], padded stride
    __shared__ float Bs[2][16][128];   // [buf][k][n]

    if (blockIdx.x >= NGEMM) {
        // ---- bucket build ----
        int t = (blockIdx.x - NGEMM) * 256 + threadIdx.x;
        const int stride = NBUK * 256;
        for (; t < kME; t += stride) {
            int m   = t / kE;
            int e   = t - m * kE;
            int src = ei[(m * 2 + 0) * kE + e];
            int dst = ei[(m * 2 + 1) * kE + e];
            int row = m * kN + dst;
            int pos = atomicAdd(&g_cnt[row], 1);
            if (pos < PAD) g_bsrc[(long)row * PAD + pos] = src;
        }
        return;
    }

    // ---- GEMM ----
    const int tid  = threadIdx.x;
    const int tr   = tid >> 4;
    const int tc   = tid & 15;
    const int row0 = tr * 8;
    const int col0 = tc * 8;
    const int rowBase = blockIdx.x * 128;

    // per-thread load coords
    const int la_r  = tid >> 2;          // A row (of 128), two halves
    const int la_c4 = (tid & 3) << 2;    // A col group of 4
    const int lb_k  = tid >> 5;          // B k row (of 16), two halves
    const int lb_n4 = (tid & 31) << 2;   // B col group of 4

    float acc[8][8];
#pragma unroll
    for (int i = 0; i < 8; i++)
#pragma unroll
        for (int j = 0; j < 8; j++) acc[i][j] = 0.f;

    // preload k0 = 0 into buffer 0
    {
#pragma unroll
        for (int i = 0; i < 2; i++) {
            int r  = la_r + i * 64;
            float4 v = make_float4(0.f, 0.f, 0.f, 0.f);
            int gr = rowBase + r;
            if (gr < kN) v = *(const float4*)(A + (long)gr * kIN + la_c4);
            As[0][la_c4 + 0][r] = v.x; As[0][la_c4 + 1][r] = v.y;
            As[0][la_c4 + 2][r] = v.z; As[0][la_c4 + 3][r] = v.w;
        }
#pragma unroll
        for (int i = 0; i < 2; i++) {
            int kk = lb_k + i * 8;
            *(float4*)(&Bs[0][kk][lb_n4]) = *(const float4*)(W + kk * kD + lb_n4);
        }
    }
    __syncthreads();

    int cur = 0;
    for (int k0 = 0; k0 < kIN; k0 += 16) {
        const int nxt = cur ^ 1;
        float4 pa[2], pb[2];
        const bool more = (k0 + 16 < kIN);
        if (more) {
#pragma unroll
            for (int i = 0; i < 2; i++) {
                int r  = la_r + i * 64;
                int gr = rowBase + r;
                pa[i] = make_float4(0.f, 0.f, 0.f, 0.f);
                if (gr < kN)
                    pa[i] = *(const float4*)(A + (long)gr * kIN + k0 + 16 + la_c4);
                pb[i] = *(const float4*)(W + (k0 + 16 + lb_k + i * 8) * kD + lb_n4);
            }
        }
#pragma unroll
        for (int kk = 0; kk < 16; kk++) {
            float ra[8], rb[8];
            *(float4*)(ra)     = *(const float4*)(&As[cur][kk][row0]);
            *(float4*)(ra + 4) = *(const float4*)(&As[cur][kk][row0 + 4]);
            *(float4*)(rb)     = *(const float4*)(&Bs[cur][kk][col0]);
            *(float4*)(rb + 4) = *(const float4*)(&Bs[cur][kk][col0 + 4]);
#pragma unroll
            for (int i = 0; i < 8; i++)
#pragma unroll
                for (int j = 0; j < 8; j++)
                    acc[i][j] = fmaf(ra[i], rb[j], acc[i][j]);
        }
        if (more) {
#pragma unroll
            for (int i = 0; i < 2; i++) {
                int r = la_r + i * 64;
                As[nxt][la_c4 + 0][r] = pa[i].x; As[nxt][la_c4 + 1][r] = pa[i].y;
                As[nxt][la_c4 + 2][r] = pa[i].z; As[nxt][la_c4 + 3][r] = pa[i].w;
                *(float4*)(&Bs[nxt][lb_k + i * 8][lb_n4]) = pb[i];
            }
        }
        __syncthreads();
        cur = nxt;
    }

    // epilogue: bias + relu; write fp32 row + packed bf16 pairs
#pragma unroll
    for (int i = 0; i < 8; i++) {
        int gr = rowBase + row0 + i;
        if (gr < kN) {
            float o[8];
#pragma unroll
            for (int j = 0; j < 8; j++)
                o[j] = fmaxf(acc[i][j] + bias[col0 + j], 0.f);
            *(float4*)(g_h + (long)gr * kD + col0)     = *(float4*)(o);
            *(float4*)(g_h + (long)gr * kD + col0 + 4) = *(float4*)(o + 4);
            unsigned* up = g_hpu + (long)gr * 64;
#pragma unroll
            for (int j = 0; j < 4; j++) {
                __nv_bfloat162 p = __floats2bfloat162_rn(o[2 * j], o[2 * j + 1]);
                int c = col0 + 2 * j;
                int ui = (tc < 8) ? c : (c - 63);  // 2l or 2l+1
                up[ui] = *(unsigned*)&p;
            }
        }
    }
}

// ---------------------------------------------------------------------------
// K2: per-node logit terms, thread per (node, head). No shuffles.
// a_dst[m,n,h] = sum_c h[n,h,c]*attn[m,h,c]; a_src uses attn[m,h,C+c].
// ---------------------------------------------------------------------------
__global__ __launch_bounds__(256) void k_alpha(const float* __restrict__ attn)
{
    __shared__ float at[kM * kH * 2 * kC];   // 1024 floats
#pragma unroll
    for (int i = 0; i < 4; i++)
        at[threadIdx.x + i * 256] = attn[threadIdx.x + i * 256];
    __syncthreads();

    int t = blockIdx.x * blockDim.x + threadIdx.x;
    if (t >= kN * kH) return;
    int n    = t >> 2;
    int head = t & 3;

    float hv[32];
#pragma unroll
    for (int i = 0; i < 8; i++)
        *(float4*)(hv + 4 * i) =
            *(const float4*)(g_h + (long)n * kD + head * kC + 4 * i);

#pragma unroll
    for (int m = 0; m < kM; m++) {
        const float* am = at + (m * kH + head) * (2 * kC);
        float dl = 0.f, dr = 0.f;
#pragma unroll
        for (int c = 0; c < kC; c++) {
            dl = fmaf(hv[c], am[c], dl);
            dr = fmaf(hv[c], am[kC + c], dr);
        }
        g_adst[((long)m * kN + n) * kH + head] = dl;
        g_asrc[((long)m * kN + n) * kH + head] = dr;
    }
}

// ---------------------------------------------------------------------------
// K3: fused aggregation + relation attention. Warp per node.
// Lane l owns channel pairs {2l,2l+1} (heads 0/1) and {64+2l,64+2l+1}
// (heads 2/3). Inner loop: 1 LDS.128 (weights+src) + 1 LDG.64 (packed
// bf16 message) + bit-trick converts + 4 FFMA + 2 FADD per message.
// ---------------------------------------------------------------------------
__global__ __launch_bounds__(256) void k_aggbeta(
    const float* __restrict__ ral, const float* __restrict__ rar,
    const float* __restrict__ rbias, float* __restrict__ outp)
{
    __shared__ float4 ssw[8][32][2];   // [warp][msg][half]: (w_q, w_{q+2}, src)
    const int w    = threadIdx.x >> 5;
    const int lane = threadIdx.x & 31;
    const int q    = lane >> 4;
    const int n    = blockIdx.x * 8 + w;
    if (n >= kN) return;

    const int h0 = q;         // head for first pair
    const int h1 = 2 + q;     // head for second pair
    const int cc = (2 * lane) & 31;

    const float2 ha  = *(const float2*)(g_h + (long)n * kD + 2 * lane);
    const float2 hbv = *(const float2*)(g_h + (long)n * kD + 64 + 2 * lane);
    const uint2* __restrict__ hp = (const uint2*)g_hpu + lane;

    float2 era[5], erb[5];
    float  bta[5], btb[5];

    for (int m = 0; m < kM; m++) {
        const int row = m * kN + n;
        const float4 ad = *(const float4*)(g_adst + (long)row * 4);
        const int cnt = min(g_cnt[row], PAD);
        const int* __restrict__ bl = g_bsrc + (long)row * PAD;
        float2 a0 = make_float2(0.f, 0.f), a1 = make_float2(0.f, 0.f);
        float d0 = 0.f, d1 = 0.f;

        for (int b0e = 0; b0e < cnt; b0e += 32) {
            const int c = min(32, cnt - b0e);
            if (lane < c) {
                int s = bl[b0e + lane];
                float4 as = *(const float4*)(g_asrc + (long)(m * kN + s) * 4);
                float l0 = ad.x + as.x; l0 = l0 > 0.f ? l0 : 0.2f * l0;
                float l1 = ad.y + as.y; l1 = l1 > 0.f ? l1 : 0.2f * l1;
                float l2 = ad.z + as.z; l2 = l2 > 0.f ? l2 : 0.2f * l2;
                float l3 = ad.w + as.w; l3 = l3 > 0.f ? l3 : 0.2f * l3;
                float w0 = __expf(l0), w1 = __expf(l1);
                float w2 = __expf(l2), w3 = __expf(l3);
                float sf = __int_as_float(s);
                ssw[w][lane][0] = make_float4(w0, w2, sf, 0.f);
                ssw[w][lane][1] = make_float4(w1, w3, sf, 0.f);
            }
            __syncwarp();
#pragma unroll 4
            for (int j = 0; j < c; j++) {
                const float4 t = ssw[w][j][q];
                const int s = __float_as_int(t.z);
                const uint2 v = hp[(long)s * 32];
                const float f0 = __int_as_float(v.x << 16);
                const float f1 = __int_as_float(v.x & 0xffff0000u);
                const float f2 = __int_as_float(v.y << 16);
                const float f3 = __int_as_float(v.y & 0xffff0000u);
                a0.x = fmaf(t.x, f0, a0.x); a0.y = fmaf(t.x, f1, a0.y);
                a1.x = fmaf(t.y, f2, a1.x); a1.y = fmaf(t.y, f3, a1.y);
                d0 += t.x; d1 += t.y;
            }
            __syncwarp();
        }
        const float i0 = 1.f / (d0 + 1e-16f);
        const float i1 = 1.f / (d1 + 1e-16f);
        era[m] = make_float2(a0.x * i0, a0.y * i0);
        erb[m] = make_float2(a1.x * i1, a1.y * i1);
    }
    era[4] = ha;   // self relation
    erb[4] = hbv;

    // beta_l = relu(h * rel_attn_l)
    const float2 rla = *(const float2*)(ral + h0 * kC + cc);
    const float2 rlb = *(const float2*)(ral + h1 * kC + cc);
    const float2 bla = make_float2(fmaxf(ha.x * rla.x, 0.f),
                                   fmaxf(ha.y * rla.y, 0.f));
    const float2 blb = make_float2(fmaxf(hbv.x * rlb.x, 0.f),
                                   fmaxf(hbv.y * rlb.y, 0.f));
#pragma unroll
    for (int r = 0; r < 5; r++) {
        const float2 rra = *(const float2*)(rar + ((r * kH + h0) * kC + cc));
        const float2 rrb = *(const float2*)(rar + ((r * kH + h1) * kC + cc));
        float bax = fmaxf(era[r].x * rra.x, 0.f);
        float bay = fmaxf(era[r].y * rra.y, 0.f);
        float bbx = fmaxf(erb[r].x * rrb.x, 0.f);
        float bby = fmaxf(erb[r].y * rrb.y, 0.f);
        float p0 = bla.x * bax + bla.y * bay;
        float p1 = blb.x * bbx + blb.y * bby;
#pragma unroll
        for (int o = 8; o > 0; o >>= 1) {
            p0 += __shfl_xor_sync(0xffffffffu, p0, o);
            p1 += __shfl_xor_sync(0xffffffffu, p1, o);
        }
        bta[r] = p0 + rbias[r];
        btb[r] = p1 + rbias[r];
    }
    // softmax over relations, then combine + relu
    float m0 = bta[0], m1 = btb[0];
#pragma unroll
    for (int r = 1; r < 5; r++) { m0 = fmaxf(m0, bta[r]); m1 = fmaxf(m1, btb[r]); }
    float s0 = 0.f, s1 = 0.f, e0[5], e1[5];
#pragma unroll
    for (int r = 0; r < 5; r++) {
        e0[r] = expf(bta[r] - m0); s0 += e0[r];
        e1[r] = expf(btb[r] - m1); s1 += e1[r];
    }
    const float is0 = 1.f / s0, is1 = 1.f / s1;
    float2 oa = make_float2(0.f, 0.f), ob = make_float2(0.f, 0.f);
#pragma unroll
    for (int r = 0; r < 5; r++) {
        const float w0 = e0[r] * is0, w1 = e1[r] * is1;
        oa.x = fmaf(w0, era[r].x, oa.x); oa.y = fmaf(w0, era[r].y, oa.y);
        ob.x = fmaf(w1, erb[r].x, ob.x); ob.y = fmaf(w1, erb[r].y, ob.y);
    }
    oa.x = fmaxf(oa.x, 0.f); oa.y = fmaxf(oa.y, 0.f);
    ob.x = fmaxf(ob.x, 0.f); ob.y = fmaxf(ob.y, 0.f);
    *(float2*)(outp + (long)n * kD + 2 * lane)      = oa;
    *(float2*)(outp + (long)n * kD + 64 + 2 * lane) = ob;
}

// ---------------------------------------------------------------------------
extern "C" void kernel_launch(void* const* d_in, const int* in_sizes, int n_in,
                              void* d_out, int out_size)
{
    const float* feats = (const float*)d_in[0];
    const int*   ei    = (const int*)d_in[1];
    const float* W     = (const float*)d_in[2];
    const float* b     = (const float*)d_in[3];
    const float* attn  = (const float*)d_in[4];
    const float* ral   = (const float*)d_in[5];
    const float* rar   = (const float*)d_in[6];
    const float* rbias = (const float*)d_in[7];
    float* outp = (float*)d_out;

    k_zero<<<(kMN + 255) / 256, 256>>>();
    k_fused<<<NGEMM + NBUK, 256>>>(feats, W, b, ei);
    k_alpha<<<(kN * kH + 255) / 256, 256>>>(attn);
    k_aggbeta<<<(kN + 7) / 8, 256>>>(ral, rar, rbias, outp);
}

// round 4
// speedup vs baseline: 1.7858x; 1.1195x over previous
#include <cuda_runtime.h>
#include <cuda_bf16.h>

// Problem constants
constexpr int kN  = 50000;   // nodes
constexpr int kE  = 800000;  // edges per metapath
constexpr int kM  = 4;       // metapaths
constexpr int kH  = 4;       // heads
constexpr int kC  = 32;      // channels per head
constexpr int kIN = 256;     // input dim
constexpr int kD  = 128;     // output dim (H*C)
constexpr int kMN = kM * kN;     // 200000
constexpr int kME = kM * kE;     // 3200000
constexpr int PAD = 64;          // bucket capacity (Poisson(16) tail ~1e-20)

constexpr int NGEMM = (kN + 127) / 128;  // 391 gemm blocks
constexpr int NBUK  = 1250;              // bucket-build blocks

// Scratch (__device__ globals; no cudaMalloc allowed)
__device__ float    g_h[kN * kD];        // projected features fp32, 25.6MB
__device__ unsigned g_hpu[kN * 64];      // packed bf16 messages, 12.8MB
                                         // u[2l+0] = bf16x2(h[2l],h[2l+1])
                                         // u[2l+1] = bf16x2(h[64+2l],h[64+2l+1])
__device__ float    g_adst[kMN * kH];    // per-(m,node) dst logit term
__device__ float    g_asrc[kMN * kH];    // per-(m,node) src logit term
__device__ int      g_cnt[kMN];          // per-(m,node) in-degree
__device__ int      g_bsrc[(long)kMN * PAD];  // padded buckets, 51.2MB

// ---------------------------------------------------------------------------
// K0: zero the degree counters
// ---------------------------------------------------------------------------
__global__ void k_zero()
{
    int i = blockIdx.x * blockDim.x + threadIdx.x;
    if (i < kMN) g_cnt[i] = 0;
}

// ---------------------------------------------------------------------------
// K1 (heterogeneous): blocks [0,NGEMM) compute h = relu(feats@W + b) with a
// double-buffered smem pipeline, writing fp32 + packed-bf16 copies AND the
// per-(m,node,head) logit terms (alpha fused into the epilogue);
// blocks [NGEMM, ...) build the padded dst-buckets (overlapped).
// ---------------------------------------------------------------------------
__global__ __launch_bounds__(256, 2) void k_fused(
    const float* __restrict__ A, const float* __restrict__ W,
    const float* __restrict__ bias, const int* __restrict__ ei,
    const float* __restrict__ attn)
{
    __shared__ float As[2][16][132];   // [buf][k][m], padded stride
    __shared__ float Bs[2][16][128];   // [buf][k][n]
    __shared__ float at[kM * kH * 2 * kC];   // 1024 floats

    if (blockIdx.x >= NGEMM) {
        // ---- bucket build ----
        int t = (blockIdx.x - NGEMM) * 256 + threadIdx.x;
        const int stride = NBUK * 256;
        for (; t < kME; t += stride) {
            int m   = t / kE;
            int e   = t - m * kE;
            int src = ei[(m * 2 + 0) * kE + e];
            int dst = ei[(m * 2 + 1) * kE + e];
            int row = m * kN + dst;
            int pos = atomicAdd(&g_cnt[row], 1);
            if (pos < PAD) g_bsrc[(long)row * PAD + pos] = src;
        }
        return;
    }

    // ---- GEMM ----
    const int tid  = threadIdx.x;
    const int tr   = tid >> 4;
    const int tc   = tid & 15;
    const int row0 = tr * 8;
    const int col0 = tc * 8;
    const int rowBase = blockIdx.x * 128;

#pragma unroll
    for (int i = 0; i < 4; i++)
        at[tid + i * 256] = attn[tid + i * 256];

    // per-thread load coords
    const int la_r  = tid >> 2;          // A row (of 128), two halves
    const int la_c4 = (tid & 3) << 2;    // A col group of 4
    const int lb_k  = tid >> 5;          // B k row (of 16), two halves
    const int lb_n4 = (tid & 31) << 2;   // B col group of 4

    float acc[8][8];
#pragma unroll
    for (int i = 0; i < 8; i++)
#pragma unroll
        for (int j = 0; j < 8; j++) acc[i][j] = 0.f;

    // preload k0 = 0 into buffer 0
    {
#pragma unroll
        for (int i = 0; i < 2; i++) {
            int r  = la_r + i * 64;
            float4 v = make_float4(0.f, 0.f, 0.f, 0.f);
            int gr = rowBase + r;
            if (gr < kN) v = *(const float4*)(A + (long)gr * kIN + la_c4);
            As[0][la_c4 + 0][r] = v.x; As[0][la_c4 + 1][r] = v.y;
            As[0][la_c4 + 2][r] = v.z; As[0][la_c4 + 3][r] = v.w;
        }
#pragma unroll
        for (int i = 0; i < 2; i++) {
            int kk = lb_k + i * 8;
            *(float4*)(&Bs[0][kk][lb_n4]) = *(const float4*)(W + kk * kD + lb_n4);
        }
    }
    __syncthreads();

    int cur = 0;
    for (int k0 = 0; k0 < kIN; k0 += 16) {
        const int nxt = cur ^ 1;
        float4 pa[2], pb[2];
        const bool more = (k0 + 16 < kIN);
        if (more) {
#pragma unroll
            for (int i = 0; i < 2; i++) {
                int r  = la_r + i * 64;
                int gr = rowBase + r;
                pa[i] = make_float4(0.f, 0.f, 0.f, 0.f);
                if (gr < kN)
                    pa[i] = *(const float4*)(A + (long)gr * kIN + k0 + 16 + la_c4);
                pb[i] = *(const float4*)(W + (k0 + 16 + lb_k + i * 8) * kD + lb_n4);
            }
        }
#pragma unroll
        for (int kk = 0; kk < 16; kk++) {
            float ra[8], rb[8];
            *(float4*)(ra)     = *(const float4*)(&As[cur][kk][row0]);
            *(float4*)(ra + 4) = *(const float4*)(&As[cur][kk][row0 + 4]);
            *(float4*)(rb)     = *(const float4*)(&Bs[cur][kk][col0]);
            *(float4*)(rb + 4) = *(const float4*)(&Bs[cur][kk][col0 + 4]);
#pragma unroll
            for (int i = 0; i < 8; i++)
#pragma unroll
                for (int j = 0; j < 8; j++)
                    acc[i][j] = fmaf(ra[i], rb[j], acc[i][j]);
        }
        if (more) {
#pragma unroll
            for (int i = 0; i < 2; i++) {
                int r = la_r + i * 64;
                As[nxt][la_c4 + 0][r] = pa[i].x; As[nxt][la_c4 + 1][r] = pa[i].y;
                As[nxt][la_c4 + 2][r] = pa[i].z; As[nxt][la_c4 + 3][r] = pa[i].w;
                *(float4*)(&Bs[nxt][lb_k + i * 8][lb_n4]) = pb[i];
            }
        }
        __syncthreads();
        cur = nxt;
    }

    // epilogue: bias + relu; write fp32 + packed bf16; fused alpha dots.
    const int hh   = tc >> 2;          // head this thread's channels belong to
    const int coff = (tc & 3) * 8;     // channel offset within head
#pragma unroll
    for (int i = 0; i < 8; i++) {
        int gr = rowBase + row0 + i;
        const bool valid = (gr < kN);
        float o[8];
#pragma unroll
        for (int j = 0; j < 8; j++)
            o[j] = fmaxf(acc[i][j] + bias[col0 + j], 0.f);
        if (valid) {
            *(float4*)(g_h + (long)gr * kD + col0)     = *(float4*)(o);
            *(float4*)(g_h + (long)gr * kD + col0 + 4) = *(float4*)(o + 4);
            unsigned* up = g_hpu + (long)gr * 64;
#pragma unroll
            for (int j = 0; j < 4; j++) {
                __nv_bfloat162 p = __floats2bfloat162_rn(o[2 * j], o[2 * j + 1]);
                int c = col0 + 2 * j;
                int ui = (tc < 8) ? c : (c - 63);  // 2l or 2l+1
                up[ui] = *(unsigned*)&p;
            }
        }
        // alpha: partial dots over this thread's 8 channels, reduce over the
        // 4 threads (shfl_xor 1,2) covering head hh's 32 channels.
#pragma unroll
        for (int m = 0; m < kM; m++) {
            const float* am = at + (m * kH + hh) * (2 * kC);
            float pl = 0.f, pr = 0.f;
#pragma unroll
            for (int j = 0; j < 8; j++) {
                pl = fmaf(o[j], am[coff + j], pl);
                pr = fmaf(o[j], am[kC + coff + j], pr);
            }
            pl += __shfl_xor_sync(0xffffffffu, pl, 1);
            pl += __shfl_xor_sync(0xffffffffu, pl, 2);
            pr += __shfl_xor_sync(0xffffffffu, pr, 1);
            pr += __shfl_xor_sync(0xffffffffu, pr, 2);
            if (valid && (tid & 3) == 0) {
                g_adst[((long)m * kN + gr) * kH + hh] = pl;
                g_asrc[((long)m * kN + gr) * kH + hh] = pr;
            }
        }
    }
}

// ---------------------------------------------------------------------------
// K3: fused aggregation + relation attention. Warp per node.
// Phase A per metapath: all <=64 edge weights computed lane-parallel into
// smem (ssh src, wsh per-half weight pairs). Phase B: gather loop with
// 8-deep LDG staging (MLP=8). Per-relation results spilled to smem so the
// kernel fits 5 blocks/SM.
// ---------------------------------------------------------------------------
__global__ __launch_bounds__(256, 5) void k_aggbeta(
    const float* __restrict__ ral, const float* __restrict__ rar,
    const float* __restrict__ rbias, float* __restrict__ outp)
{
    __shared__ int    ssh[8][PAD];            // src per msg
    __shared__ float2 wsh[8][PAD][2];         // (w_h0,w_h1) per msg per half
    __shared__ float4 sera[8][kM][32];        // spilled era/erb per metapath
    const int w    = threadIdx.x >> 5;
    const int lane = threadIdx.x & 31;
    const int q    = lane >> 4;
    const int n    = blockIdx.x * 8 + w;
    if (n >= kN) return;

    const uint2* __restrict__ hp = (const uint2*)g_hpu + lane;

    for (int m = 0; m < kM; m++) {
        const int row = m * kN + n;
        const float4 ad = *(const float4*)(g_adst + (long)row * 4);
        const int cnt = min(g_cnt[row], PAD);
        const int* __restrict__ bl = g_bsrc + (long)row * PAD;

        // Phase A: weights (lane-parallel, <=2 iterations)
        for (int b = lane; b < cnt; b += 32) {
            int s = bl[b];
            float4 as = *(const float4*)(g_asrc + (long)(m * kN + s) * 4);
            float l0 = ad.x + as.x; l0 = l0 > 0.f ? l0 : 0.2f * l0;
            float l1 = ad.y + as.y; l1 = l1 > 0.f ? l1 : 0.2f * l1;
            float l2 = ad.z + as.z; l2 = l2 > 0.f ? l2 : 0.2f * l2;
            float l3 = ad.w + as.w; l3 = l3 > 0.f ? l3 : 0.2f * l3;
            ssh[w][b]    = s;
            wsh[w][b][0] = make_float2(__expf(l0), __expf(l2));
            wsh[w][b][1] = make_float2(__expf(l1), __expf(l3));
        }
        __syncwarp();

        // Phase B: gather with 8-deep staging
        float2 a0 = make_float2(0.f, 0.f), a1 = make_float2(0.f, 0.f);
        float d0 = 0.f, d1 = 0.f;
        int jb = 0;
        for (; jb + 8 <= cnt; jb += 8) {
            uint2 v[8];
#pragma unroll
            for (int k = 0; k < 8; k++) {
                int s = ssh[w][jb + k];
                v[k] = hp[(long)s * 32];
            }
#pragma unroll
            for (int k = 0; k < 8; k++) {
                const float2 t = wsh[w][jb + k][q];
                const float f0 = __int_as_float(v[k].x << 16);
                const float f1 = __int_as_float(v[k].x & 0xffff0000u);
                const float f2 = __int_as_float(v[k].y << 16);
                const float f3 = __int_as_float(v[k].y & 0xffff0000u);
                a0.x = fmaf(t.x, f0, a0.x); a0.y = fmaf(t.x, f1, a0.y);
                a1.x = fmaf(t.y, f2, a1.x); a1.y = fmaf(t.y, f3, a1.y);
                d0 += t.x; d1 += t.y;
            }
        }
        for (; jb < cnt; jb++) {
            int s = ssh[w][jb];
            uint2 v = hp[(long)s * 32];
            const float2 t = wsh[w][jb][q];
            const float f0 = __int_as_float(v.x << 16);
            const float f1 = __int_as_float(v.x & 0xffff0000u);
            const float f2 = __int_as_float(v.y << 16);
            const float f3 = __int_as_float(v.y & 0xffff0000u);
            a0.x = fmaf(t.x, f0, a0.x); a0.y = fmaf(t.x, f1, a0.y);
            a1.x = fmaf(t.y, f2, a1.x); a1.y = fmaf(t.y, f3, a1.y);
            d0 += t.x; d1 += t.y;
        }
        const float i0 = 1.f / (d0 + 1e-16f);
        const float i1 = 1.f / (d1 + 1e-16f);
        sera[w][m][lane] = make_float4(a0.x * i0, a0.y * i0,
                                       a1.x * i1, a1.y * i1);
        __syncwarp();
    }

    // ---- beta phase ----
    const int h0 = q;
    const int h1 = 2 + q;
    const int cc = (2 * lane) & 31;

    const float2 ha  = *(const float2*)(g_h + (long)n * kD + 2 * lane);
    const float2 hbv = *(const float2*)(g_h + (long)n * kD + 64 + 2 * lane);

    float2 era[5], erb[5];
#pragma unroll
    for (int r = 0; r < 4; r++) {
        float4 t = sera[w][r][lane];
        era[r] = make_float2(t.x, t.y);
        erb[r] = make_float2(t.z, t.w);
    }
    era[4] = ha;   // self relation
    erb[4] = hbv;

    float bta[5], btb[5];
    const float2 rla = *(const float2*)(ral + h0 * kC + cc);
    const float2 rlb = *(const float2*)(ral + h1 * kC + cc);
    const float2 bla = make_float2(fmaxf(ha.x * rla.x, 0.f),
                                   fmaxf(ha.y * rla.y, 0.f));
    const float2 blb = make_float2(fmaxf(hbv.x * rlb.x, 0.f),
                                   fmaxf(hbv.y * rlb.y, 0.f));
#pragma unroll
    for (int r = 0; r < 5; r++) {
        const float2 rra = *(const float2*)(rar + ((r * kH + h0) * kC + cc));
        const float2 rrb = *(const float2*)(rar + ((r * kH + h1) * kC + cc));
        float bax = fmaxf(era[r].x * rra.x, 0.f);
        float bay = fmaxf(era[r].y * rra.y, 0.f);
        float bbx = fmaxf(erb[r].x * rrb.x, 0.f);
        float bby = fmaxf(erb[r].y * rrb.y, 0.f);
        float p0 = bla.x * bax + bla.y * bay;
        float p1 = blb.x * bbx + blb.y * bby;
#pragma unroll
        for (int o = 8; o > 0; o >>= 1) {
            p0 += __shfl_xor_sync(0xffffffffu, p0, o);
            p1 += __shfl_xor_sync(0xffffffffu, p1, o);
        }
        bta[r] = p0 + rbias[r];
        btb[r] = p1 + rbias[r];
    }
    // softmax over relations, then combine + relu
    float m0 = bta[0], m1 = btb[0];
#pragma unroll
    for (int r = 1; r < 5; r++) { m0 = fmaxf(m0, bta[r]); m1 = fmaxf(m1, btb[r]); }
    float s0 = 0.f, s1 = 0.f, e0[5], e1[5];
#pragma unroll
    for (int r = 0; r < 5; r++) {
        e0[r] = expf(bta[r] - m0); s0 += e0[r];
        e1[r] = expf(btb[r] - m1); s1 += e1[r];
    }
    const float is0 = 1.f / s0, is1 = 1.f / s1;
    float2 oa = make_float2(0.f, 0.f), ob = make_float2(0.f, 0.f);
#pragma unroll
    for (int r = 0; r < 5; r++) {
        const float w0 = e0[r] * is0, w1 = e1[r] * is1;
        oa.x = fmaf(w0, era[r].x, oa.x); oa.y = fmaf(w0, era[r].y, oa.y);
        ob.x = fmaf(w1, erb[r].x, ob.x); ob.y = fmaf(w1, erb[r].y, ob.y);
    }
    oa.x = fmaxf(oa.x, 0.f); oa.y = fmaxf(oa.y, 0.f);
    ob.x = fmaxf(ob.x, 0.f); ob.y = fmaxf(ob.y, 0.f);
    *(float2*)(outp + (long)n * kD + 2 * lane)      = oa;
    *(float2*)(outp + (long)n * kD + 64 + 2 * lane) = ob;
}

// ---------------------------------------------------------------------------
extern "C" void kernel_launch(void* const* d_in, const int* in_sizes, int n_in,
                              void* d_out, int out_size)
{
    const float* feats = (const float*)d_in[0];
    const int*   ei    = (const int*)d_in[1];
    const float* W     = (const float*)d_in[2];
    const float* b     = (const float*)d_in[3];
    const float* attn  = (const float*)d_in[4];
    const float* ral   = (const float*)d_in[5];
    const float* rar   = (const float*)d_in[6];
    const float* rbias = (const float*)d_in[7];
    float* outp = (float*)d_out;

    k_zero<<<(kMN + 255) / 256, 256>>>();
    k_fused<<<NGEMM + NBUK, 256>>>(feats, W, b, ei, attn);
    k_aggbeta<<<(kN + 7) / 8, 256>>>(ral, rar, rbias, outp);
}